// round 3
// baseline (speedup 1.0000x reference)
#include <cuda_runtime.h>
#include <cstdint>

#define N_MAX 50000
#define E_MAX 800000

// ---------------- scratch (__device__ globals; no allocs allowed) ----------
__device__ int   g_deg_in[N_MAX];
__device__ int   g_deg_out[N_MAX];
__device__ int   g_row_start[N_MAX + 1];
__device__ int   g_cursor[N_MAX];
__device__ int   g_csr_src[E_MAX];
__device__ float g_norm_src[N_MAX];

__device__ __forceinline__ uint32_t f2tf32(float v) {
    uint32_t r;
    asm("cvt.rna.tf32.f32 %0, %1;" : "=r"(r) : "f"(v));
    return r;
}

__device__ __forceinline__ void mma_tf32(float c[4], uint32_t a0, uint32_t a1,
                                         uint32_t a2, uint32_t a3,
                                         uint32_t b0, uint32_t b1) {
    asm volatile(
        "mma.sync.aligned.m16n8k8.row.col.f32.tf32.tf32.f32 "
        "{%0,%1,%2,%3}, {%4,%5,%6,%7}, {%8,%9}, {%0,%1,%2,%3};"
        : "+f"(c[0]), "+f"(c[1]), "+f"(c[2]), "+f"(c[3])
        : "r"(a0), "r"(a1), "r"(a2), "r"(a3), "r"(b0), "r"(b1));
}

// ---------------- prep kernels ----------------------------------------------
__global__ void k_init(int n) {
    int i = blockIdx.x * blockDim.x + threadIdx.x;
    if (i < n) { g_deg_in[i] = 0; g_deg_out[i] = 0; g_cursor[i] = 0; }
}

__global__ void k_count(const int* __restrict__ ei, int e) {
    int i = blockIdx.x * blockDim.x + threadIdx.x;
    if (i < e) {
        atomicAdd(&g_deg_out[ei[i]], 1);
        atomicAdd(&g_deg_in[ei[e + i]], 1);
    }
}

// exclusive scan of deg_in -> row_start; single block, Kogge-Stone over partials
__global__ void k_scan(int n) {
    __shared__ int part[1024];
    int t = threadIdx.x;
    int chunk = (n + 1023) / 1024;
    int beg = t * chunk;
    int end = min(beg + chunk, n);
    int own = 0;
    for (int i = beg; i < end; ++i) own += g_deg_in[i];
    part[t] = own;
    __syncthreads();
#pragma unroll
    for (int off = 1; off < 1024; off <<= 1) {
        int v = (t >= off) ? part[t - off] : 0;
        __syncthreads();
        part[t] += v;
        __syncthreads();
    }
    if (t == 1023) g_row_start[n] = part[1023];
    int run = part[t] - own;   // exclusive prefix
    for (int i = beg; i < end; ++i) { g_row_start[i] = run; run += g_deg_in[i]; }
}

__global__ void k_fill_norm(const int* __restrict__ ei, int e, int n) {
    int i = blockIdx.x * blockDim.x + threadIdx.x;
    if (i < n) g_norm_src[i] = rsqrtf(fmaxf((float)g_deg_out[i], 1.0f));
    if (i < e) {
        int s = ei[i];
        int d = ei[e + i];
        int pos = atomicAdd(&g_cursor[d], 1);
        g_csr_src[g_row_start[d] + pos] = s;
    }
}

// ---------------- fused aggregate + tf32 mma.sync GEMM -----------------------
// dyn smem:
//   sBias : 128 f32                       [0, 512)
//   sA    : 128 x 132 u32 (tf32 bits)     [512, 68096)     pitch 132 dodges conflicts
//   sBf   : B fragments [nt][ks][lane][2] [68096, 133632)
#define A_PITCH  132
#define SM_BIAS  0
#define SM_A     512
#define SM_BF    (512 + 128 * A_PITCH * 4)
#define SM_TOTAL (SM_BF + 16 * 16 * 32 * 2 * 4)

__global__ __launch_bounds__(256, 1)
void k_fused(const float* __restrict__ x, const float* __restrict__ Wm,
             const float* __restrict__ bias, float* __restrict__ out, int n) {
    extern __shared__ char smem[];
    float*    sBias = (float*)(smem + SM_BIAS);
    uint32_t* sA    = (uint32_t*)(smem + SM_A);
    uint2*    sBf   = (uint2*)(smem + SM_BF);

    int tid = threadIdx.x;
    int wid = tid >> 5;
    int lid = tid & 31;
    int rowBase = blockIdx.x * 128;

    if (tid < 128) sBias[tid] = bias[tid];

    // ---- stage W into mma B-fragment layout (k-major W[k][n], 16384 elems) ----
#pragma unroll
    for (int i = 0; i < 64; ++i) {
        int idx = tid + i * 256;
        int k = idx >> 7;
        int nn = idx & 127;
        int nt = nn >> 3, ks = k >> 3;
        int lane = ((nn & 7) << 2) | (k & 3);
        int slot = (k >> 2) & 1;
        ((uint32_t*)&sBf[(nt * 16 + ks) * 32 + lane])[slot] = f2tf32(Wm[idx]);
    }

    // ---- aggregate 128 destination rows into sA (tf32) ----
    const float4* xv = reinterpret_cast<const float4*>(x);
    for (int j = 0; j < 16; ++j) {
        int r = wid * 16 + j;
        int grow = rowBase + r;
        float ax = 0.f, ay = 0.f, az = 0.f, aw = 0.f;
        int deg = 0;
        if (grow < n) {
            int beg = g_row_start[grow];
            int end = g_row_start[grow + 1];
            deg = end - beg;
            int idx = beg;
            for (; idx + 4 <= end; idx += 4) {
                int s0 = g_csr_src[idx], s1 = g_csr_src[idx + 1];
                int s2 = g_csr_src[idx + 2], s3 = g_csr_src[idx + 3];
                float n0 = g_norm_src[s0], n1 = g_norm_src[s1];
                float n2 = g_norm_src[s2], n3 = g_norm_src[s3];
                float4 v0 = xv[(size_t)s0 * 32 + lid];
                float4 v1 = xv[(size_t)s1 * 32 + lid];
                float4 v2 = xv[(size_t)s2 * 32 + lid];
                float4 v3 = xv[(size_t)s3 * 32 + lid];
                ax = fmaf(v0.x, n0, ax); ay = fmaf(v0.y, n0, ay);
                az = fmaf(v0.z, n0, az); aw = fmaf(v0.w, n0, aw);
                ax = fmaf(v1.x, n1, ax); ay = fmaf(v1.y, n1, ay);
                az = fmaf(v1.z, n1, az); aw = fmaf(v1.w, n1, aw);
                ax = fmaf(v2.x, n2, ax); ay = fmaf(v2.y, n2, ay);
                az = fmaf(v2.z, n2, az); aw = fmaf(v2.w, n2, aw);
                ax = fmaf(v3.x, n3, ax); ay = fmaf(v3.y, n3, ay);
                az = fmaf(v3.z, n3, az); aw = fmaf(v3.w, n3, aw);
            }
            for (; idx < end; ++idx) {
                int s0 = g_csr_src[idx];
                float n0 = g_norm_src[s0];
                float4 v0 = xv[(size_t)s0 * 32 + lid];
                ax = fmaf(v0.x, n0, ax); ay = fmaf(v0.y, n0, ay);
                az = fmaf(v0.z, n0, az); aw = fmaf(v0.w, n0, aw);
            }
        }
        float nd = rsqrtf(fmaxf((float)deg, 1.0f));
        uint4 t;
        t.x = f2tf32(ax * nd); t.y = f2tf32(ay * nd);
        t.z = f2tf32(az * nd); t.w = f2tf32(aw * nd);
        *(uint4*)&sA[r * A_PITCH + lid * 4] = t;   // aligned: 528B pitch, 16B offsets
    }
    __syncthreads();

    // ---- GEMM: each warp -> rows [wid*16, wid*16+16), all 128 cols ----
    float acc[16][4];
#pragma unroll
    for (int nt = 0; nt < 16; ++nt)
#pragma unroll
        for (int q = 0; q < 4; ++q) acc[nt][q] = 0.f;

    int m0 = wid * 16 + (lid >> 2);    // fragment rows m0, m0+8
#pragma unroll
    for (int ks = 0; ks < 16; ++ks) {
        int k0 = ks * 8 + (lid & 3);
        uint32_t a0 = sA[m0 * A_PITCH + k0];
        uint32_t a1 = sA[(m0 + 8) * A_PITCH + k0];
        uint32_t a2 = sA[m0 * A_PITCH + k0 + 4];
        uint32_t a3 = sA[(m0 + 8) * A_PITCH + k0 + 4];
#pragma unroll
        for (int nt = 0; nt < 16; ++nt) {
            uint2 b = sBf[(nt * 16 + ks) * 32 + lid];
            mma_tf32(acc[nt], a0, a1, a2, a3, b.x, b.y);
        }
    }

    // ---- epilogue: bias + relu, store from C fragments ----
    int r0 = rowBase + m0;             // rows r0, r0+8
#pragma unroll
    for (int nt = 0; nt < 16; ++nt) {
        int col = nt * 8 + (lid & 3) * 2;
        float b0 = sBias[col], b1 = sBias[col + 1];
        if (r0 < n) {
            float2 v;
            v.x = fmaxf(acc[nt][0] + b0, 0.f);
            v.y = fmaxf(acc[nt][1] + b1, 0.f);
            *(float2*)&out[(size_t)r0 * 128 + col] = v;
        }
        if (r0 + 8 < n) {
            float2 v;
            v.x = fmaxf(acc[nt][2] + b0, 0.f);
            v.y = fmaxf(acc[nt][3] + b1, 0.f);
            *(float2*)&out[(size_t)(r0 + 8) * 128 + col] = v;
        }
    }
}

// ---------------- launch ----------------------------------------------------
extern "C" void kernel_launch(void* const* d_in, const int* in_sizes, int n_in,
                              void* d_out, int out_size) {
    const float* x    = (const float*)d_in[0];
    const int*   ei   = (const int*)d_in[1];
    const float* Wm   = (const float*)d_in[2];
    const float* bias = (const float*)d_in[3];
    float* out = (float*)d_out;

    int n = in_sizes[0] / 128;   // 50000
    int e = in_sizes[1] / 2;     // 800000

    cudaFuncSetAttribute(k_fused, cudaFuncAttributeMaxDynamicSharedMemorySize, SM_TOTAL);

    k_init<<<(n + 255) / 256, 256>>>(n);
    k_count<<<(e + 255) / 256, 256>>>(ei, e);
    k_scan<<<1, 1024>>>(n);
    k_fill_norm<<<(e + 255) / 256, 256>>>(ei, e, n);
    k_fused<<<(n + 127) / 128, 256, SM_TOTAL>>>(x, Wm, bias, out, n);
}